// round 1
// baseline (speedup 1.0000x reference)
#include <cuda_runtime.h>
#include <cuda_bf16.h>
#include <math_constants.h>

#define B 4
#define NPTS 1024
#define KNB 80

// ---------------- scratch (device globals; no allocation allowed) ----------------
__device__ float g_G[(size_t)B * NPTS * NPTS];          // gram matrices
__device__ float g_xx[B * NPTS];                        // squared norms
__device__ int   g_idx[B * NPTS * KNB];                 // knn indices
__device__ float g_u[(size_t)B * NPTS * 128];           // (b,n,o) W1·x
__device__ float g_v[(size_t)B * NPTS * 128];           // (b,n,o) (W2-W1)·x
__device__ float g_ymaxE[(size_t)B * NPTS * 128];       // per (b,n,o) max_k y
__device__ float g_yminE[(size_t)B * NPTS * 128];
__device__ double g_gs[64];                             // edge-layer group sums
__device__ unsigned int g_ymax[B * 1024];               // final head max/min (encoded)
__device__ unsigned int g_ymin[B * 1024];
__device__ double g_gs5[64];                            // final head group sums

// monotone float<->uint encoding for atomic max/min
__device__ __forceinline__ unsigned int fenc(float f) {
    unsigned int b = __float_as_uint(f);
    return (b & 0x80000000u) ? ~b : (b | 0x80000000u);
}
__device__ __forceinline__ float fdec(unsigned int u) {
    unsigned int b = (u & 0x80000000u) ? (u & 0x7FFFFFFFu) : ~u;
    return __uint_as_float(b);
}

// ---------------- zero kernels ----------------
__global__ void zero_gs_kernel() {
    if (threadIdx.x < 64) g_gs[threadIdx.x] = 0.0;
}
__global__ void zero_final_kernel() {
    int i = blockIdx.x * 256 + threadIdx.x;
    if (i < B * 1024) { g_ymax[i] = 0u; g_ymin[i] = 0xFFFFFFFFu; }
    if (i < 64) g_gs5[i] = 0.0;
}

// ---------------- squared norms ----------------
__global__ void xx_kernel(const float* __restrict__ x, int bstride, int C) {
    int i = blockIdx.x * 256 + threadIdx.x;
    if (i >= B * NPTS) return;
    int b = i >> 10, n = i & 1023;
    const float* xb = x + (size_t)b * bstride + n;
    float s = 0.f;
    for (int c = 0; c < C; c++) { float v = xb[c * NPTS]; s += v * v; }
    g_xx[i] = s;
}

// ---------------- gram: G[b] = x^T x, tiled 64x64 ----------------
__global__ void gram_kernel(const float* __restrict__ x, int bstride, int C) {
    int b = blockIdx.z;
    int n0 = blockIdx.y * 64, m0 = blockIdx.x * 64;
    __shared__ float As[32][65];
    __shared__ float Bs[32][65];
    int t = threadIdx.x;
    int tx = t & 15, ty = t >> 4;
    float acc[4][4] = {};
    const float* xb = x + (size_t)b * bstride;
    for (int cc = 0; cc < C; cc += 32) {
        int CH = min(32, C - cc);
        for (int i = t; i < 32 * 64; i += 256) {
            int c = i >> 6, l = i & 63;
            float av = 0.f, bv = 0.f;
            if (c < CH) {
                av = xb[(size_t)(cc + c) * NPTS + n0 + l];
                bv = xb[(size_t)(cc + c) * NPTS + m0 + l];
            }
            As[c][l] = av; Bs[c][l] = bv;
        }
        __syncthreads();
        for (int c = 0; c < CH; c++) {
            float a[4], bb[4];
#pragma unroll
            for (int i = 0; i < 4; i++) { a[i] = As[c][ty * 4 + i]; bb[i] = Bs[c][tx * 4 + i]; }
#pragma unroll
            for (int i = 0; i < 4; i++)
#pragma unroll
                for (int j = 0; j < 4; j++) acc[i][j] = fmaf(a[i], bb[j], acc[i][j]);
        }
        __syncthreads();
    }
    float* Gb = g_G + ((size_t)b << 20);
#pragma unroll
    for (int i = 0; i < 4; i++)
#pragma unroll
        for (int j = 0; j < 4; j++)
            Gb[(size_t)(n0 + ty * 4 + i) * NPTS + m0 + tx * 4 + j] = acc[i][j];
}

// ---------------- knn: exact top-80 per row (ties -> lowest index) ----------------
__global__ void knn_kernel() {
    int bn = blockIdx.x;
    int b = bn >> 10, n = bn & 1023;
    __shared__ unsigned long long keys[NPTS];
    __shared__ unsigned long long wred[8];
    const float* Grow = g_G + ((size_t)b << 20) + ((size_t)n << 10);
    const float* xxb = g_xx + (b << 10);
    float xxn = xxb[n];
    int t = threadIdx.x;
#pragma unroll
    for (int i = t; i < NPTS; i += 256) {
        float nd = 2.f * Grow[i] - xxn - xxb[i];
        keys[i] = ((unsigned long long)fenc(nd) << 32) | (unsigned int)(1023 - i);
    }
    __syncthreads();
    int* out = g_idx + bn * KNB;
    for (int r = 0; r < KNB; r++) {
        unsigned long long best = 0ull;
#pragma unroll
        for (int i = t; i < NPTS; i += 256) {
            unsigned long long k = keys[i];
            if (k > best) best = k;
        }
#pragma unroll
        for (int off = 16; off > 0; off >>= 1) {
            unsigned long long o = __shfl_down_sync(0xffffffffu, best, off);
            if (o > best) best = o;
        }
        if ((t & 31) == 0) wred[t >> 5] = best;
        __syncthreads();
        if (t < 8) {
            best = wred[t];
#pragma unroll
            for (int off = 4; off > 0; off >>= 1) {
                unsigned long long o = __shfl_down_sync(0xffu, best, off);
                if (o > best) best = o;
            }
            if (t == 0) {
                int m = 1023 - (int)(best & 0xFFFFFFFFull);
                out[r] = m;
                keys[m] = 0ull;
            }
        }
        __syncthreads();
    }
}

// ---------------- u/v projections: u=W1 x, v=(W2-W1) x, layout (b,n,o) ----------------
__global__ void uv_kernel(const float* __restrict__ x, int bstride,
                          const float* __restrict__ W, int Cin, int Cout) {
    int tid = blockIdx.x * blockDim.x + threadIdx.x;
    int total = B * NPTS * Cout;
    if (tid >= total) return;
    int o = tid % Cout;
    int n = (tid / Cout) & 1023;
    int b = tid / (Cout * NPTS);
    const float* xb = x + (size_t)b * bstride + n;
    const float* w = W + (size_t)o * 2 * Cin;
    float u = 0.f, v = 0.f;
    for (int c = 0; c < Cin; c++) {
        float xv = xb[(size_t)c * NPTS];
        float w1 = w[c], w2 = w[Cin + c];
        u = fmaf(w1, xv, u);
        v = fmaf(w2 - w1, xv, v);
    }
    g_u[tid] = u;
    g_v[tid] = v;
}

// ---------------- gather + max/min + group stats ----------------
__global__ void edge_agg_kernel(int Cout) {
    int bn = blockIdx.x;
    int b = bn >> 10;
    int o = threadIdx.x;
    const int* idxr = g_idx + bn * KNB;
    float mx = -CUDART_INF_F, mn = CUDART_INF_F, s1 = 0.f, s2 = 0.f;
    const float* ub = g_u + ((size_t)b << 10) * Cout;
    for (int k = 0; k < KNB; k++) {
        int j = idxr[k];
        float val = ub[(size_t)j * Cout + o];
        mx = fmaxf(mx, val); mn = fminf(mn, val);
        s1 += val; s2 = fmaf(val, val, s2);
    }
    float v = g_v[(size_t)bn * Cout + o];
    float ymax = mx + v, ymin = mn + v;
    g_ymaxE[(size_t)bn * Cout + o] = ymax;
    g_yminE[(size_t)bn * Cout + o] = ymin;
    float S1 = s1 + (float)KNB * v;
    float S2 = s2 + 2.f * v * s1 + (float)KNB * v * v;
#pragma unroll
    for (int off = 16; off > 0; off >>= 1) {
        S1 += __shfl_down_sync(0xffffffffu, S1, off);
        S2 += __shfl_down_sync(0xffffffffu, S2, off);
    }
    if ((o & 31) == 0) {
        int g = o / (Cout / 2);
        atomicAdd(&g_gs[(b * 2 + g) * 2 + 0], (double)S1);
        atomicAdd(&g_gs[(b * 2 + g) * 2 + 1], (double)S2);
    }
}

// ---------------- GN + leaky + write layer output into x_features ----------------
__global__ void edge_out_kernel(int Cout, const float* __restrict__ gnw,
                                const float* __restrict__ gnb,
                                float* __restrict__ feat, int choff) {
    int bo = blockIdx.x;
    int b = bo / Cout, o = bo % Cout;
    int g = o / (Cout / 2);
    double cnt = (double)(Cout / 2) * (double)NPTS * (double)KNB;
    double S1 = g_gs[(b * 2 + g) * 2 + 0], S2 = g_gs[(b * 2 + g) * 2 + 1];
    double mud = S1 / cnt;
    float var = (float)(S2 / cnt - mud * mud);
    float mu = (float)mud;
    float rs = rsqrtf(var + 1e-5f);
    float a = gnw[o] * rs;
    float bb = gnb[o] - mu * a;
    float* orow = feat + (size_t)b * (256 * NPTS) + (size_t)(choff + o) * NPTS;
    const float* mxr = g_ymaxE + ((size_t)b << 10) * Cout + o;
    const float* mnr = g_yminE + ((size_t)b << 10) * Cout + o;
    for (int n = threadIdx.x; n < NPTS; n += blockDim.x) {
        float c1 = fmaf(a, mxr[(size_t)n * Cout], bb);
        float c2 = fmaf(a, mnr[(size_t)n * Cout], bb);
        c1 = c1 >= 0.f ? c1 : 0.2f * c1;
        c2 = c2 >= 0.f ? c2 : 0.2f * c2;
        orow[n] = fmaxf(c1, c2);
    }
}

// ---------------- final head matmul (1024x256 @ 256x1024) with fused stats ----------------
__global__ void final_mm_kernel(const float* __restrict__ feat,
                                const float* __restrict__ W,
                                const float* __restrict__ bias) {
    int b = blockIdx.z;
    int co0 = blockIdx.x * 64;
    int n0 = blockIdx.y * 64;
    __shared__ float Ws[32][65];
    __shared__ float Xs[32][65];
    int t = threadIdx.x, tx = t & 15, ty = t >> 4;
    float acc[4][4] = {};
    const float* fb = feat + (size_t)b * 262144;
    for (int cc = 0; cc < 256; cc += 32) {
        for (int i = t; i < 2048; i += 256) {
            int col = i & 31, row = i >> 5;  // row = co_l, col = c (coalesced along c)
            Ws[col][row] = W[(size_t)(co0 + row) * 256 + cc + col];
        }
        for (int i = t; i < 2048; i += 256) {
            int nl = i & 63, c = i >> 6;
            Xs[c][nl] = fb[(size_t)(cc + c) * NPTS + n0 + nl];
        }
        __syncthreads();
#pragma unroll
        for (int c = 0; c < 32; c++) {
            float wv[4], xv[4];
#pragma unroll
            for (int i = 0; i < 4; i++) { wv[i] = Ws[c][ty * 4 + i]; xv[i] = Xs[c][tx * 4 + i]; }
#pragma unroll
            for (int i = 0; i < 4; i++)
#pragma unroll
                for (int j = 0; j < 4; j++) acc[i][j] = fmaf(wv[i], xv[j], acc[i][j]);
        }
        __syncthreads();
    }
    float s1t = 0.f, s2t = 0.f;
#pragma unroll
    for (int i = 0; i < 4; i++) {
        int co = co0 + ty * 4 + i;
        float bv = bias[co];
        float mx = -CUDART_INF_F, mn = CUDART_INF_F;
#pragma unroll
        for (int j = 0; j < 4; j++) {
            float y = acc[i][j] + bv;
            mx = fmaxf(mx, y); mn = fminf(mn, y);
            s1t += y; s2t = fmaf(y, y, s2t);
        }
#pragma unroll
        for (int off = 8; off > 0; off >>= 1) {
            mx = fmaxf(mx, __shfl_down_sync(0xffffffffu, mx, off, 16));
            mn = fminf(mn, __shfl_down_sync(0xffffffffu, mn, off, 16));
        }
        if (tx == 0) {
            atomicMax(&g_ymax[b * 1024 + co], fenc(mx));
            atomicMin(&g_ymin[b * 1024 + co], fenc(mn));
        }
    }
#pragma unroll
    for (int off = 16; off > 0; off >>= 1) {
        s1t += __shfl_down_sync(0xffffffffu, s1t, off);
        s2t += __shfl_down_sync(0xffffffffu, s2t, off);
    }
    __shared__ double sred[8][2];
    int w = t >> 5, lane = t & 31;
    if (lane == 0) { sred[w][0] = (double)s1t; sred[w][1] = (double)s2t; }
    __syncthreads();
    if (t == 0) {
        double a = 0.0, c = 0.0;
        for (int i = 0; i < 8; i++) { a += sred[i][0]; c += sred[i][1]; }
        int g = co0 >> 7;
        atomicAdd(&g_gs5[(b * 8 + g) * 2 + 0], a);
        atomicAdd(&g_gs5[(b * 8 + g) * 2 + 1], c);
    }
}

// ---------------- final head: GN + relu + max-over-N via endpoints ----------------
__global__ void final_out_kernel(const float* __restrict__ gnw,
                                 const float* __restrict__ gnb,
                                 float* __restrict__ out) {
    int i = blockIdx.x * 256 + threadIdx.x;
    if (i >= B * 1024) return;
    int b = i >> 10, c = i & 1023;
    int g = c >> 7;
    double cnt = 128.0 * 1024.0;
    double S1 = g_gs5[(b * 8 + g) * 2 + 0], S2 = g_gs5[(b * 8 + g) * 2 + 1];
    double mud = S1 / cnt;
    float var = (float)(S2 / cnt - mud * mud);
    float mu = (float)mud;
    float rs = rsqrtf(var + 1e-5f);
    float a = gnw[c] * rs;
    float bb = gnb[c] - mu * a;
    float ymx = fdec(g_ymax[i]), ymn = fdec(g_ymin[i]);
    float c1 = fmaxf(fmaf(a, ymx, bb), 0.f);
    float c2 = fmaxf(fmaf(a, ymn, bb), 0.f);
    out[i] = fmaxf(c1, c2);
}

// ---------------- launch ----------------
extern "C" void kernel_launch(void* const* d_in, const int* in_sizes, int n_in,
                              void* d_out, int out_size) {
    const float* x    = (const float*)d_in[0];
    const float* c1w  = (const float*)d_in[1];
    const float* g1w  = (const float*)d_in[2];
    const float* g1b  = (const float*)d_in[3];
    const float* c2w  = (const float*)d_in[4];
    const float* g2w  = (const float*)d_in[5];
    const float* g2b  = (const float*)d_in[6];
    const float* c3w  = (const float*)d_in[7];
    const float* g3w  = (const float*)d_in[8];
    const float* g3b  = (const float*)d_in[9];
    const float* mlpw = (const float*)d_in[10];
    const float* mlpb = (const float*)d_in[11];
    const float* g5w  = (const float*)d_in[12];
    const float* g5b  = (const float*)d_in[13];

    float* out  = (float*)d_out;
    float* feat = out + B * 1024;  // x_features region (B,256,N)

    struct L { const float* xin; int bstride, Cin, Cout, choff;
               const float* W; const float* gw; const float* gb; };
    L layers[3] = {
        { x,                3 * NPTS,   3,   64, 0,   c1w, g1w, g1b },
        { feat,             256 * NPTS, 64,  64, 64,  c2w, g2w, g2b },
        { feat + 64 * NPTS, 256 * NPTS, 64,  128, 128, c3w, g3w, g3b },
    };

    for (int li = 0; li < 3; li++) {
        L& l = layers[li];
        zero_gs_kernel<<<1, 64>>>();
        xx_kernel<<<16, 256>>>(l.xin, l.bstride, l.Cin);
        gram_kernel<<<dim3(16, 16, B), 256>>>(l.xin, l.bstride, l.Cin);
        knn_kernel<<<B * NPTS, 256>>>();
        int tot = B * NPTS * l.Cout;
        uv_kernel<<<tot / 256, 256>>>(l.xin, l.bstride, l.W, l.Cin, l.Cout);
        edge_agg_kernel<<<B * NPTS, l.Cout>>>(l.Cout);
        edge_out_kernel<<<B * l.Cout, 256>>>(l.Cout, l.gw, l.gb, feat, l.choff);
    }

    zero_final_kernel<<<16, 256>>>();
    final_mm_kernel<<<dim3(16, 16, B), 256>>>(feat, mlpw, mlpb);
    final_out_kernel<<<16, 256>>>(g5w, g5b, out);
}

// round 2
// speedup vs baseline: 1.7683x; 1.7683x over previous
#include <cuda_runtime.h>
#include <cuda_bf16.h>
#include <math_constants.h>

#define B 4
#define NPTS 1024
#define KNB 80

// ---------------- scratch (device globals; no allocation allowed) ----------------
__device__ float g_G[(size_t)B * NPTS * NPTS];          // gram matrices
__device__ float g_xx[B * NPTS];                        // squared norms
__device__ int   g_idx[B * NPTS * KNB];                 // knn indices
__device__ float g_u[(size_t)B * NPTS * 128];           // (b,n,o) W1·x
__device__ float g_v[(size_t)B * NPTS * 128];           // (b,n,o) (W2-W1)·x
__device__ float g_ymaxE[(size_t)B * NPTS * 128];       // per (b,n,o) max_k y
__device__ float g_yminE[(size_t)B * NPTS * 128];
__device__ double g_gs[64];                             // edge-layer group sums
__device__ unsigned int g_ymax[B * 1024];               // final head max/min (encoded)
__device__ unsigned int g_ymin[B * 1024];
__device__ double g_gs5[64];                            // final head group sums

// monotone float<->uint encoding for atomic max/min
__device__ __forceinline__ unsigned int fenc(float f) {
    unsigned int b = __float_as_uint(f);
    return (b & 0x80000000u) ? ~b : (b | 0x80000000u);
}
__device__ __forceinline__ float fdec(unsigned int u) {
    unsigned int b = (u & 0x80000000u) ? (u & 0x7FFFFFFFu) : ~u;
    return __uint_as_float(b);
}

// ---------------- zero kernels ----------------
__global__ void zero_gs_kernel() {
    if (threadIdx.x < 64) g_gs[threadIdx.x] = 0.0;
}
__global__ void zero_final_kernel() {
    int i = blockIdx.x * 256 + threadIdx.x;
    if (i < B * 1024) { g_ymax[i] = 0u; g_ymin[i] = 0xFFFFFFFFu; }
    if (i < 64) g_gs5[i] = 0.0;
}

// ---------------- squared norms ----------------
__global__ void xx_kernel(const float* __restrict__ x, int bstride, int C) {
    int i = blockIdx.x * 256 + threadIdx.x;
    if (i >= B * NPTS) return;
    int b = i >> 10, n = i & 1023;
    const float* xb = x + (size_t)b * bstride + n;
    float s = 0.f;
    for (int c = 0; c < C; c++) { float v = xb[c * NPTS]; s += v * v; }
    g_xx[i] = s;
}

// ---------------- gram: G[b] = x^T x, tiled 64x64 ----------------
__global__ void gram_kernel(const float* __restrict__ x, int bstride, int C) {
    int b = blockIdx.z;
    int n0 = blockIdx.y * 64, m0 = blockIdx.x * 64;
    __shared__ float As[32][65];
    __shared__ float Bs[32][65];
    int t = threadIdx.x;
    int tx = t & 15, ty = t >> 4;
    float acc[4][4] = {};
    const float* xb = x + (size_t)b * bstride;
    for (int cc = 0; cc < C; cc += 32) {
        int CH = min(32, C - cc);
        for (int i = t; i < 32 * 64; i += 256) {
            int c = i >> 6, l = i & 63;
            float av = 0.f, bv = 0.f;
            if (c < CH) {
                av = xb[(size_t)(cc + c) * NPTS + n0 + l];
                bv = xb[(size_t)(cc + c) * NPTS + m0 + l];
            }
            As[c][l] = av; Bs[c][l] = bv;
        }
        __syncthreads();
        for (int c = 0; c < CH; c++) {
            float a[4], bb[4];
#pragma unroll
            for (int i = 0; i < 4; i++) { a[i] = As[c][ty * 4 + i]; bb[i] = Bs[c][tx * 4 + i]; }
#pragma unroll
            for (int i = 0; i < 4; i++)
#pragma unroll
                for (int j = 0; j < 4; j++) acc[i][j] = fmaf(a[i], bb[j], acc[i][j]);
        }
        __syncthreads();
    }
    float* Gb = g_G + ((size_t)b << 20);
#pragma unroll
    for (int i = 0; i < 4; i++)
#pragma unroll
        for (int j = 0; j < 4; j++)
            Gb[(size_t)(n0 + ty * 4 + i) * NPTS + m0 + tx * 4 + j] = acc[i][j];
}

// ---------------- knn: top-80 per row via 4-pass MSB radix select ----------------
// Downstream consumes the neighbor SET only (max/min/sum are symmetric), so
// order inside the set is irrelevant. Ties at the threshold value are broken
// by lowest index (matching jax.lax.top_k set semantics).
__global__ void knn_kernel() {
    int bn = blockIdx.x;
    int b = bn >> 10, n = bn & 1023;
    __shared__ unsigned int skeys[NPTS];
    __shared__ int hist[256];
    __shared__ int s_bsel, s_above, s_cnt, s_ecnt;
    __shared__ int s_eq[128];   // equal-to-threshold index list (typically 1 entry)
    const float* Grow = g_G + ((size_t)b << 20) + ((size_t)n << 10);
    const float* xxb = g_xx + (b << 10);
    float xxn = xxb[n];
    int t = threadIdx.x;
    unsigned int rkeys[4];
#pragma unroll
    for (int j = 0; j < 4; j++) {
        int i = t + 256 * j;
        float nd = 2.f * Grow[i] - xxn - xxb[i];
        unsigned int k = fenc(nd);
        rkeys[j] = k;
        skeys[i] = k;
    }
    unsigned int prefix = 0, pmask = 0;
    int need = KNB;
    for (int shift = 24; shift >= 0; shift -= 8) {
        hist[t] = 0;
        __syncthreads();
#pragma unroll
        for (int j = 0; j < 4; j++) {
            unsigned int k = rkeys[j];
            if ((k & pmask) == prefix) atomicAdd(&hist[(k >> shift) & 255], 1);
        }
        __syncthreads();
        // in-place suffix sum over 256 bins
#pragma unroll
        for (int off = 1; off < 256; off <<= 1) {
            int w = (t + off < 256) ? hist[t + off] : 0;
            __syncthreads();
            hist[t] += w;
            __syncthreads();
        }
        int sfx = hist[t];
        int nxt = (t < 255) ? hist[t + 1] : 0;
        if (sfx >= need && nxt < need) { s_bsel = t; s_above = nxt; }
        __syncthreads();
        prefix |= ((unsigned int)s_bsel) << shift;
        pmask  |= 255u << shift;
        need   -= s_above;   // elements strictly above this bin are all in
        __syncthreads();
    }
    // collection: all keys > prefix are in (any order); 'need' equals remain
    if (t == 0) { s_cnt = 0; s_ecnt = 0; }
    __syncthreads();
    int* out = g_idx + bn * KNB;
#pragma unroll
    for (int j = 0; j < 4; j++) {
        unsigned int k = rkeys[j];
        if (k > prefix) {
            int p = atomicAdd(&s_cnt, 1);
            out[p] = t + 256 * j;
        } else if (k == prefix) {
            int p = atomicAdd(&s_ecnt, 1);
            if (p < 128) s_eq[p] = t + 256 * j;
        }
    }
    __syncthreads();
    if (t == 0) {
        int p = s_cnt;           // == KNB - need
        int L = s_ecnt;
        if (L == need && L <= 128) {
            // exact fit: order within set irrelevant
            for (int i = 0; i < L; i++) out[p++] = s_eq[i];
        } else if (L <= 128) {
            // pick 'need' smallest indices from the small list
            for (int r = 0; r < need; r++) {
                int bi = -1, bv = 0x7FFFFFFF;
                for (int i = 0; i < L; i++) {
                    int v = s_eq[i];
                    if (v >= 0 && v < bv) { bv = v; bi = i; }
                }
                out[p++] = bv;
                s_eq[bi] = -1;
            }
        } else {
            // pathological many-ties fallback: ordered scan
            for (int i = 0; i < NPTS && p < KNB; i++)
                if (skeys[i] == prefix) out[p++] = i;
        }
    }
}

// ---------------- u/v projections: u=W1 x, v=(W2-W1) x, layout (b,n,o) ----------------
__global__ void uv_kernel(const float* __restrict__ x, int bstride,
                          const float* __restrict__ W, int Cin, int Cout) {
    int tid = blockIdx.x * blockDim.x + threadIdx.x;
    int total = B * NPTS * Cout;
    if (tid >= total) return;
    int o = tid % Cout;
    int n = (tid / Cout) & 1023;
    int b = tid / (Cout * NPTS);
    const float* xb = x + (size_t)b * bstride + n;
    const float* w = W + (size_t)o * 2 * Cin;
    float u = 0.f, v = 0.f;
    for (int c = 0; c < Cin; c++) {
        float xv = xb[(size_t)c * NPTS];
        float w1 = w[c], w2 = w[Cin + c];
        u = fmaf(w1, xv, u);
        v = fmaf(w2 - w1, xv, v);
    }
    g_u[tid] = u;
    g_v[tid] = v;
}

// ---------------- gather + max/min + group stats ----------------
__global__ void edge_agg_kernel(int Cout) {
    int bn = blockIdx.x;
    int b = bn >> 10;
    int o = threadIdx.x;
    const int* idxr = g_idx + bn * KNB;
    float mx = -CUDART_INF_F, mn = CUDART_INF_F, s1 = 0.f, s2 = 0.f;
    const float* ub = g_u + ((size_t)b << 10) * Cout;
    for (int k = 0; k < KNB; k++) {
        int j = idxr[k];
        float val = ub[(size_t)j * Cout + o];
        mx = fmaxf(mx, val); mn = fminf(mn, val);
        s1 += val; s2 = fmaf(val, val, s2);
    }
    float v = g_v[(size_t)bn * Cout + o];
    float ymax = mx + v, ymin = mn + v;
    g_ymaxE[(size_t)bn * Cout + o] = ymax;
    g_yminE[(size_t)bn * Cout + o] = ymin;
    float S1 = s1 + (float)KNB * v;
    float S2 = s2 + 2.f * v * s1 + (float)KNB * v * v;
#pragma unroll
    for (int off = 16; off > 0; off >>= 1) {
        S1 += __shfl_down_sync(0xffffffffu, S1, off);
        S2 += __shfl_down_sync(0xffffffffu, S2, off);
    }
    if ((o & 31) == 0) {
        int g = o / (Cout / 2);
        atomicAdd(&g_gs[(b * 2 + g) * 2 + 0], (double)S1);
        atomicAdd(&g_gs[(b * 2 + g) * 2 + 1], (double)S2);
    }
}

// ---------------- GN + leaky + write layer output into x_features ----------------
__global__ void edge_out_kernel(int Cout, const float* __restrict__ gnw,
                                const float* __restrict__ gnb,
                                float* __restrict__ feat, int choff) {
    int bo = blockIdx.x;
    int b = bo / Cout, o = bo % Cout;
    int g = o / (Cout / 2);
    double cnt = (double)(Cout / 2) * (double)NPTS * (double)KNB;
    double S1 = g_gs[(b * 2 + g) * 2 + 0], S2 = g_gs[(b * 2 + g) * 2 + 1];
    double mud = S1 / cnt;
    float var = (float)(S2 / cnt - mud * mud);
    float mu = (float)mud;
    float rs = rsqrtf(var + 1e-5f);
    float a = gnw[o] * rs;
    float bb = gnb[o] - mu * a;
    float* orow = feat + (size_t)b * (256 * NPTS) + (size_t)(choff + o) * NPTS;
    const float* mxr = g_ymaxE + ((size_t)b << 10) * Cout + o;
    const float* mnr = g_yminE + ((size_t)b << 10) * Cout + o;
    for (int n = threadIdx.x; n < NPTS; n += blockDim.x) {
        float c1 = fmaf(a, mxr[(size_t)n * Cout], bb);
        float c2 = fmaf(a, mnr[(size_t)n * Cout], bb);
        c1 = c1 >= 0.f ? c1 : 0.2f * c1;
        c2 = c2 >= 0.f ? c2 : 0.2f * c2;
        orow[n] = fmaxf(c1, c2);
    }
}

// ---------------- final head matmul (1024x256 @ 256x1024) with fused stats ----------------
__global__ void final_mm_kernel(const float* __restrict__ feat,
                                const float* __restrict__ W,
                                const float* __restrict__ bias) {
    int b = blockIdx.z;
    int co0 = blockIdx.x * 64;
    int n0 = blockIdx.y * 64;
    __shared__ float Ws[32][65];
    __shared__ float Xs[32][65];
    int t = threadIdx.x, tx = t & 15, ty = t >> 4;
    float acc[4][4] = {};
    const float* fb = feat + (size_t)b * 262144;
    for (int cc = 0; cc < 256; cc += 32) {
        for (int i = t; i < 2048; i += 256) {
            int col = i & 31, row = i >> 5;  // row = co_l, col = c (coalesced along c)
            Ws[col][row] = W[(size_t)(co0 + row) * 256 + cc + col];
        }
        for (int i = t; i < 2048; i += 256) {
            int nl = i & 63, c = i >> 6;
            Xs[c][nl] = fb[(size_t)(cc + c) * NPTS + n0 + nl];
        }
        __syncthreads();
#pragma unroll
        for (int c = 0; c < 32; c++) {
            float wv[4], xv[4];
#pragma unroll
            for (int i = 0; i < 4; i++) { wv[i] = Ws[c][ty * 4 + i]; xv[i] = Xs[c][tx * 4 + i]; }
#pragma unroll
            for (int i = 0; i < 4; i++)
#pragma unroll
                for (int j = 0; j < 4; j++) acc[i][j] = fmaf(wv[i], xv[j], acc[i][j]);
        }
        __syncthreads();
    }
    float s1t = 0.f, s2t = 0.f;
#pragma unroll
    for (int i = 0; i < 4; i++) {
        int co = co0 + ty * 4 + i;
        float bv = bias[co];
        float mx = -CUDART_INF_F, mn = CUDART_INF_F;
#pragma unroll
        for (int j = 0; j < 4; j++) {
            float y = acc[i][j] + bv;
            mx = fmaxf(mx, y); mn = fminf(mn, y);
            s1t += y; s2t = fmaf(y, y, s2t);
        }
#pragma unroll
        for (int off = 8; off > 0; off >>= 1) {
            mx = fmaxf(mx, __shfl_down_sync(0xffffffffu, mx, off, 16));
            mn = fminf(mn, __shfl_down_sync(0xffffffffu, mn, off, 16));
        }
        if (tx == 0) {
            atomicMax(&g_ymax[b * 1024 + co], fenc(mx));
            atomicMin(&g_ymin[b * 1024 + co], fenc(mn));
        }
    }
#pragma unroll
    for (int off = 16; off > 0; off >>= 1) {
        s1t += __shfl_down_sync(0xffffffffu, s1t, off);
        s2t += __shfl_down_sync(0xffffffffu, s2t, off);
    }
    __shared__ double sred[8][2];
    int w = t >> 5, lane = t & 31;
    if (lane == 0) { sred[w][0] = (double)s1t; sred[w][1] = (double)s2t; }
    __syncthreads();
    if (t == 0) {
        double a = 0.0, c = 0.0;
        for (int i = 0; i < 8; i++) { a += sred[i][0]; c += sred[i][1]; }
        int g = co0 >> 7;
        atomicAdd(&g_gs5[(b * 8 + g) * 2 + 0], a);
        atomicAdd(&g_gs5[(b * 8 + g) * 2 + 1], c);
    }
}

// ---------------- final head: GN + relu + max-over-N via endpoints ----------------
__global__ void final_out_kernel(const float* __restrict__ gnw,
                                 const float* __restrict__ gnb,
                                 float* __restrict__ out) {
    int i = blockIdx.x * 256 + threadIdx.x;
    if (i >= B * 1024) return;
    int b = i >> 10, c = i & 1023;
    int g = c >> 7;
    double cnt = 128.0 * 1024.0;
    double S1 = g_gs5[(b * 8 + g) * 2 + 0], S2 = g_gs5[(b * 8 + g) * 2 + 1];
    double mud = S1 / cnt;
    float var = (float)(S2 / cnt - mud * mud);
    float mu = (float)mud;
    float rs = rsqrtf(var + 1e-5f);
    float a = gnw[c] * rs;
    float bb = gnb[c] - mu * a;
    float ymx = fdec(g_ymax[i]), ymn = fdec(g_ymin[i]);
    float c1 = fmaxf(fmaf(a, ymx, bb), 0.f);
    float c2 = fmaxf(fmaf(a, ymn, bb), 0.f);
    out[i] = fmaxf(c1, c2);
}

// ---------------- launch ----------------
extern "C" void kernel_launch(void* const* d_in, const int* in_sizes, int n_in,
                              void* d_out, int out_size) {
    const float* x    = (const float*)d_in[0];
    const float* c1w  = (const float*)d_in[1];
    const float* g1w  = (const float*)d_in[2];
    const float* g1b  = (const float*)d_in[3];
    const float* c2w  = (const float*)d_in[4];
    const float* g2w  = (const float*)d_in[5];
    const float* g2b  = (const float*)d_in[6];
    const float* c3w  = (const float*)d_in[7];
    const float* g3w  = (const float*)d_in[8];
    const float* g3b  = (const float*)d_in[9];
    const float* mlpw = (const float*)d_in[10];
    const float* mlpb = (const float*)d_in[11];
    const float* g5w  = (const float*)d_in[12];
    const float* g5b  = (const float*)d_in[13];

    float* out  = (float*)d_out;
    float* feat = out + B * 1024;  // x_features region (B,256,N)

    struct L { const float* xin; int bstride, Cin, Cout, choff;
               const float* W; const float* gw; const float* gb; };
    L layers[3] = {
        { x,                3 * NPTS,   3,   64, 0,   c1w, g1w, g1b },
        { feat,             256 * NPTS, 64,  64, 64,  c2w, g2w, g2b },
        { feat + 64 * NPTS, 256 * NPTS, 64,  128, 128, c3w, g3w, g3b },
    };

    for (int li = 0; li < 3; li++) {
        L& l = layers[li];
        zero_gs_kernel<<<1, 64>>>();
        xx_kernel<<<16, 256>>>(l.xin, l.bstride, l.Cin);
        gram_kernel<<<dim3(16, 16, B), 256>>>(l.xin, l.bstride, l.Cin);
        knn_kernel<<<B * NPTS, 256>>>();
        int tot = B * NPTS * l.Cout;
        uv_kernel<<<tot / 256, 256>>>(l.xin, l.bstride, l.W, l.Cin, l.Cout);
        edge_agg_kernel<<<B * NPTS, l.Cout>>>(l.Cout);
        edge_out_kernel<<<B * l.Cout, 256>>>(l.Cout, l.gw, l.gb, feat, l.choff);
    }

    zero_final_kernel<<<16, 256>>>();
    final_mm_kernel<<<dim3(16, 16, B), 256>>>(feat, mlpw, mlpb);
    final_out_kernel<<<16, 256>>>(g5w, g5b, out);
}

// round 3
// speedup vs baseline: 1.9885x; 1.1245x over previous
#include <cuda_runtime.h>
#include <cuda_bf16.h>
#include <math_constants.h>

#define B 4
#define NPTS 1024
#define KNB 80

// ---------------- scratch (device globals; no allocation allowed) ----------------
__device__ float g_G[(size_t)B * NPTS * NPTS];          // neg_dist matrices
__device__ int   g_idx[B * NPTS * KNB];                 // knn indices
__device__ float g_u[(size_t)B * NPTS * 128];           // (b,n,o) W1·x
__device__ float g_v[(size_t)B * NPTS * 128];           // (b,n,o) (W2-W1)·x
__device__ float g_ymaxE[(size_t)B * NPTS * 128];       // per (b,n,o) max_k y
__device__ float g_yminE[(size_t)B * NPTS * 128];
__device__ double g_gs[48];                             // edge-layer group sums (16/layer)
__device__ unsigned int g_ymax[B * 1024];               // final head max/min (encoded)
__device__ unsigned int g_ymin[B * 1024];
__device__ double g_gs5[64];                            // final head group sums

// monotone float<->uint encoding for atomic max/min
__device__ __forceinline__ unsigned int fenc(float f) {
    unsigned int b = __float_as_uint(f);
    return (b & 0x80000000u) ? ~b : (b | 0x80000000u);
}
__device__ __forceinline__ float fdec(unsigned int u) {
    unsigned int b = (u & 0x80000000u) ? (u & 0x7FFFFFFFu) : ~u;
    return __uint_as_float(b);
}

// ---------------- one upfront zero kernel ----------------
__global__ void zero_all_kernel() {
    int i = blockIdx.x * 256 + threadIdx.x;
    if (i < B * 1024) { g_ymax[i] = 0u; g_ymin[i] = 0xFFFFFFFFu; }
    if (i < 48) g_gs[i] = 0.0;
    if (i < 64) g_gs5[i] = 0.0;
}

// ---------------- gram + fused xx: writes neg_dist = 2*x^T x - xx_n - xx_m ----------------
// 128x128 tile, 256 threads, 8x8 per thread
__global__ void gram_kernel(const float* __restrict__ x, int bstride, int C) {
    int b = blockIdx.z;
    int n0 = blockIdx.y * 128, m0 = blockIdx.x * 128;
    __shared__ float As[32][132];
    __shared__ float Bs[32][132];
    int t = threadIdx.x;
    int tx = t & 15, ty = t >> 4;
    float acc[8][8] = {};
    float sa[8] = {}, sb[8] = {};
    const float* xb = x + (size_t)b * bstride;
    for (int cc = 0; cc < C; cc += 32) {
        int CH = min(32, C - cc);
        for (int i = t; i < 32 * 128; i += 256) {
            int c = i >> 7, l = i & 127;
            float av = 0.f, bv = 0.f;
            if (c < CH) {
                av = xb[(size_t)(cc + c) * NPTS + n0 + l];
                bv = xb[(size_t)(cc + c) * NPTS + m0 + l];
            }
            As[c][l] = av; Bs[c][l] = bv;
        }
        __syncthreads();
        for (int c = 0; c < CH; c++) {
            float a[8], bb[8];
            const float4* a4 = (const float4*)&As[c][ty * 8];
            const float4* b4 = (const float4*)&Bs[c][tx * 8];
            float4 av0 = a4[0], av1 = a4[1];
            float4 bv0 = b4[0], bv1 = b4[1];
            a[0]=av0.x;a[1]=av0.y;a[2]=av0.z;a[3]=av0.w;a[4]=av1.x;a[5]=av1.y;a[6]=av1.z;a[7]=av1.w;
            bb[0]=bv0.x;bb[1]=bv0.y;bb[2]=bv0.z;bb[3]=bv0.w;bb[4]=bv1.x;bb[5]=bv1.y;bb[6]=bv1.z;bb[7]=bv1.w;
#pragma unroll
            for (int i = 0; i < 8; i++) sa[i] = fmaf(a[i], a[i], sa[i]);
#pragma unroll
            for (int j = 0; j < 8; j++) sb[j] = fmaf(bb[j], bb[j], sb[j]);
#pragma unroll
            for (int i = 0; i < 8; i++)
#pragma unroll
                for (int j = 0; j < 8; j++) acc[i][j] = fmaf(a[i], bb[j], acc[i][j]);
        }
        __syncthreads();
    }
    float* Gb = g_G + ((size_t)b << 20);
#pragma unroll
    for (int i = 0; i < 8; i++) {
        float* row = Gb + (size_t)(n0 + ty * 8 + i) * NPTS + m0 + tx * 8;
#pragma unroll
        for (int j = 0; j < 8; j++)
            row[j] = 2.f * acc[i][j] - sa[i] - sb[j];
    }
}

// ---------------- knn: top-80 per row via 4-pass MSB radix select ----------------
__global__ void knn_kernel() {
    int bn = blockIdx.x;
    int b = bn >> 10;
    __shared__ unsigned int skeys[NPTS];
    __shared__ int hist[256];
    __shared__ int wtot[8];
    __shared__ int s_bsel, s_above, s_cnt, s_ecnt;
    __shared__ int s_eq[128];
    const float* nd = g_G + ((size_t)b << 20) + ((size_t)(bn & 1023) << 10);
    int t = threadIdx.x;
    int lane = t & 31, w = t >> 5;
    unsigned int rkeys[4];
#pragma unroll
    for (int j = 0; j < 4; j++) {
        int i = t + 256 * j;
        unsigned int k = fenc(nd[i]);
        rkeys[j] = k;
        skeys[i] = k;
    }
    unsigned int prefix = 0, pmask = 0;
    int need = KNB;
    for (int shift = 24; shift >= 0; shift -= 8) {
        hist[t] = 0;
        __syncthreads();
#pragma unroll
        for (int j = 0; j < 4; j++) {
            unsigned int k = rkeys[j];
            if ((k & pmask) == prefix) atomicAdd(&hist[(k >> shift) & 255], 1);
        }
        __syncthreads();
        int c = hist[t];
        int s = c;
#pragma unroll
        for (int off = 1; off < 32; off <<= 1) {
            int o = __shfl_down_sync(0xffffffffu, s, off);
            if (lane + off < 32) s += o;
        }
        if (lane == 0) wtot[w] = s;
        __syncthreads();
        int offsum = 0;
        for (int w2 = w + 1; w2 < 8; w2++) offsum += wtot[w2];
        int sfx = s + offsum;
        int nxt = sfx - c;
        if (sfx >= need && nxt < need) { s_bsel = t; s_above = nxt; }
        __syncthreads();
        prefix |= ((unsigned int)s_bsel) << shift;
        pmask  |= 255u << shift;
        need   -= s_above;
        __syncthreads();
    }
    if (t == 0) { s_cnt = 0; s_ecnt = 0; }
    __syncthreads();
    int* out = g_idx + bn * KNB;
#pragma unroll
    for (int j = 0; j < 4; j++) {
        unsigned int k = rkeys[j];
        if (k > prefix) {
            int p = atomicAdd(&s_cnt, 1);
            out[p] = t + 256 * j;
        } else if (k == prefix) {
            int p = atomicAdd(&s_ecnt, 1);
            if (p < 128) s_eq[p] = t + 256 * j;
        }
    }
    __syncthreads();
    if (t == 0) {
        int p = s_cnt;           // == KNB - need
        int L = s_ecnt;
        if (L == need && L <= 128) {
            for (int i = 0; i < L; i++) out[p++] = s_eq[i];
        } else if (L <= 128) {
            for (int r = 0; r < need; r++) {
                int bi = -1, bv = 0x7FFFFFFF;
                for (int i = 0; i < L; i++) {
                    int v = s_eq[i];
                    if (v >= 0 && v < bv) { bv = v; bi = i; }
                }
                out[p++] = bv;
                s_eq[bi] = -1;
            }
        } else {
            for (int i = 0; i < NPTS && p < KNB; i++)
                if (skeys[i] == prefix) out[p++] = i;
        }
    }
}

// ---------------- u/v projections: u=W1 x, v=(W2-W1) x, layout (b,n,o) ----------------
__global__ void uv_kernel(const float* __restrict__ x, int bstride,
                          const float* __restrict__ W, int Cin, int Cout) {
    int tid = blockIdx.x * blockDim.x + threadIdx.x;
    int total = B * NPTS * Cout;
    if (tid >= total) return;
    int o = tid % Cout;
    int n = (tid / Cout) & 1023;
    int b = tid / (Cout * NPTS);
    const float* xb = x + (size_t)b * bstride + n;
    const float* w = W + (size_t)o * 2 * Cin;
    float u = 0.f, v = 0.f;
    for (int c = 0; c < Cin; c++) {
        float xv = xb[(size_t)c * NPTS];
        float w1 = w[c], w2 = w[Cin + c];
        u = fmaf(w1, xv, u);
        v = fmaf(w2 - w1, xv, v);
    }
    g_u[tid] = u;
    g_v[tid] = v;
}

// ---------------- gather + max/min + group stats (float4) ----------------
__global__ void edge_agg_kernel(int Cout, int gsoff) {
    int TPP = Cout >> 2;          // threads per point (16 or 32)
    int ppb = 256 / TPP;          // points per block (16 or 8)
    int t = threadIdx.x;
    int p = t / TPP, o4 = t % TPP;
    int bn = blockIdx.x * ppb + p;
    int b = bn >> 10;
    __shared__ int sidx[16][KNB];
    __shared__ double sacc[4];
    if (t < 4) sacc[t] = 0.0;
    for (int i = t; i < ppb * KNB; i += 256)
        sidx[i / KNB][i % KNB] = g_idx[(blockIdx.x * ppb + i / KNB) * KNB + i % KNB];
    __syncthreads();
    int rs = Cout >> 2;
    const float4* ub = (const float4*)g_u + ((size_t)(b << 10)) * rs;
    float4 mx = make_float4(-CUDART_INF_F, -CUDART_INF_F, -CUDART_INF_F, -CUDART_INF_F);
    float4 mn = make_float4(CUDART_INF_F, CUDART_INF_F, CUDART_INF_F, CUDART_INF_F);
    float4 s1 = make_float4(0, 0, 0, 0), s2 = make_float4(0, 0, 0, 0);
    const int* myidx = sidx[p];
    for (int k = 0; k < KNB; k++) {
        int j = myidx[k];
        float4 vv = ub[(size_t)j * rs + o4];
        mx.x = fmaxf(mx.x, vv.x); mn.x = fminf(mn.x, vv.x); s1.x += vv.x; s2.x = fmaf(vv.x, vv.x, s2.x);
        mx.y = fmaxf(mx.y, vv.y); mn.y = fminf(mn.y, vv.y); s1.y += vv.y; s2.y = fmaf(vv.y, vv.y, s2.y);
        mx.z = fmaxf(mx.z, vv.z); mn.z = fminf(mn.z, vv.z); s1.z += vv.z; s2.z = fmaf(vv.z, vv.z, s2.z);
        mx.w = fmaxf(mx.w, vv.w); mn.w = fminf(mn.w, vv.w); s1.w += vv.w; s2.w = fmaf(vv.w, vv.w, s2.w);
    }
    float4 v = ((const float4*)g_v)[(size_t)bn * rs + o4];
    float4 ymx = make_float4(mx.x + v.x, mx.y + v.y, mx.z + v.z, mx.w + v.w);
    float4 ymn = make_float4(mn.x + v.x, mn.y + v.y, mn.z + v.z, mn.w + v.w);
    ((float4*)g_ymaxE)[(size_t)bn * rs + o4] = ymx;
    ((float4*)g_yminE)[(size_t)bn * rs + o4] = ymn;
    const float Kf = (float)KNB;
    float S1 = (s1.x + Kf * v.x) + (s1.y + Kf * v.y) + (s1.z + Kf * v.z) + (s1.w + Kf * v.w);
    float S2 = (s2.x + 2.f * v.x * s1.x + Kf * v.x * v.x)
             + (s2.y + 2.f * v.y * s1.y + Kf * v.y * v.y)
             + (s2.z + 2.f * v.z * s1.z + Kf * v.z * v.z)
             + (s2.w + 2.f * v.w * s1.w + Kf * v.w * v.w);
    int half = TPP >> 1;                // lanes per group segment
    int lane = t & 31;
#pragma unroll
    for (int off = 16; off > 0; off >>= 1) {
        if (off < half) {
            S1 += __shfl_down_sync(0xffffffffu, S1, off, half);
            S2 += __shfl_down_sync(0xffffffffu, S2, off, half);
        } else if (off == half) {
            // nothing: boundary handled by segment width
        }
    }
    // redo cleanly: segmented reduce of width 'half'
    // (the loop above only handled off<half; add off for widths)
    // NOTE: shfl with width=half does segmented reduction:
    // done above for off = half/2 ... 1 when off < half.
    if ((lane & (half - 1)) == 0) {
        int g = (lane / half) & 1;
        atomicAdd(&sacc[g * 2 + 0], (double)S1);
        atomicAdd(&sacc[g * 2 + 1], (double)S2);
    }
    __syncthreads();
    if (t == 0) {
        atomicAdd(&g_gs[gsoff + (b * 2 + 0) * 2 + 0], sacc[0]);
        atomicAdd(&g_gs[gsoff + (b * 2 + 0) * 2 + 1], sacc[1]);
        atomicAdd(&g_gs[gsoff + (b * 2 + 1) * 2 + 0], sacc[2]);
        atomicAdd(&g_gs[gsoff + (b * 2 + 1) * 2 + 1], sacc[3]);
    }
}

// ---------------- GN + leaky + write layer output into x_features ----------------
__global__ void edge_out_kernel(int Cout, int gsoff, const float* __restrict__ gnw,
                                const float* __restrict__ gnb,
                                float* __restrict__ feat, int choff) {
    int bo = blockIdx.x;
    int b = bo / Cout, o = bo % Cout;
    int g = o / (Cout / 2);
    double cnt = (double)(Cout / 2) * (double)NPTS * (double)KNB;
    double S1 = g_gs[gsoff + (b * 2 + g) * 2 + 0], S2 = g_gs[gsoff + (b * 2 + g) * 2 + 1];
    double mud = S1 / cnt;
    float var = (float)(S2 / cnt - mud * mud);
    float mu = (float)mud;
    float rs = rsqrtf(var + 1e-5f);
    float a = gnw[o] * rs;
    float bb = gnb[o] - mu * a;
    float* orow = feat + (size_t)b * (256 * NPTS) + (size_t)(choff + o) * NPTS;
    const float* mxr = g_ymaxE + ((size_t)(b << 10)) * Cout + o;
    const float* mnr = g_yminE + ((size_t)(b << 10)) * Cout + o;
    for (int n = threadIdx.x; n < NPTS; n += blockDim.x) {
        float c1 = fmaf(a, mxr[(size_t)n * Cout], bb);
        float c2 = fmaf(a, mnr[(size_t)n * Cout], bb);
        c1 = c1 >= 0.f ? c1 : 0.2f * c1;
        c2 = c2 >= 0.f ? c2 : 0.2f * c2;
        orow[n] = fmaxf(c1, c2);
    }
}

// ---------------- final head matmul: 128x128 tile, 8x8/thread, fused stats ----------------
__global__ void final_mm_kernel(const float* __restrict__ feat,
                                const float* __restrict__ W,
                                const float* __restrict__ bias) {
    int b = blockIdx.z;
    int co0 = blockIdx.x * 128;
    int n0 = blockIdx.y * 128;
    __shared__ float Ws[32][132];
    __shared__ float Xs[32][128];
    int t = threadIdx.x, tx = t & 15, ty = t >> 4;
    int lane = t & 31, w = t >> 5;
    float acc[8][8] = {};
    const float* fb = feat + (size_t)b * 262144;
    for (int cc = 0; cc < 256; cc += 32) {
        for (int i = t; i < 32 * 128; i += 256) {
            int row = i >> 5, c = i & 31;
            Ws[c][row] = W[(size_t)(co0 + row) * 256 + cc + c];
        }
        for (int i = t; i < 32 * 128; i += 256) {
            int nl = i & 127, c = i >> 7;
            Xs[c][nl] = fb[(size_t)(cc + c) * NPTS + n0 + nl];
        }
        __syncthreads();
#pragma unroll
        for (int c = 0; c < 32; c++) {
            float wv[8], xv[8];
            const float4* w4 = (const float4*)&Ws[c][ty * 8];
            const float4* x4 = (const float4*)&Xs[c][tx * 8];
            float4 a0 = w4[0], a1 = w4[1], b0 = x4[0], b1 = x4[1];
            wv[0]=a0.x;wv[1]=a0.y;wv[2]=a0.z;wv[3]=a0.w;wv[4]=a1.x;wv[5]=a1.y;wv[6]=a1.z;wv[7]=a1.w;
            xv[0]=b0.x;xv[1]=b0.y;xv[2]=b0.z;xv[3]=b0.w;xv[4]=b1.x;xv[5]=b1.y;xv[6]=b1.z;xv[7]=b1.w;
#pragma unroll
            for (int i = 0; i < 8; i++)
#pragma unroll
                for (int j = 0; j < 8; j++) acc[i][j] = fmaf(wv[i], xv[j], acc[i][j]);
        }
        __syncthreads();
    }
    float s1t = 0.f, s2t = 0.f;
#pragma unroll
    for (int i = 0; i < 8; i++) {
        int co = co0 + ty * 8 + i;
        float bv = bias[co];
        float mx = -CUDART_INF_F, mn = CUDART_INF_F;
#pragma unroll
        for (int j = 0; j < 8; j++) {
            float y = acc[i][j] + bv;
            mx = fmaxf(mx, y); mn = fminf(mn, y);
            s1t += y; s2t = fmaf(y, y, s2t);
        }
#pragma unroll
        for (int off = 8; off > 0; off >>= 1) {
            mx = fmaxf(mx, __shfl_down_sync(0xffffffffu, mx, off, 16));
            mn = fminf(mn, __shfl_down_sync(0xffffffffu, mn, off, 16));
        }
        if (tx == 0) {
            atomicMax(&g_ymax[b * 1024 + co], fenc(mx));
            atomicMin(&g_ymin[b * 1024 + co], fenc(mn));
        }
    }
#pragma unroll
    for (int off = 16; off > 0; off >>= 1) {
        s1t += __shfl_down_sync(0xffffffffu, s1t, off);
        s2t += __shfl_down_sync(0xffffffffu, s2t, off);
    }
    __shared__ double sred[8][2];
    if (lane == 0) { sred[w][0] = (double)s1t; sred[w][1] = (double)s2t; }
    __syncthreads();
    if (t == 0) {
        double a = 0.0, c = 0.0;
        for (int i = 0; i < 8; i++) { a += sred[i][0]; c += sred[i][1]; }
        int g = blockIdx.x;   // co-tile == group (128 channels)
        atomicAdd(&g_gs5[(b * 8 + g) * 2 + 0], a);
        atomicAdd(&g_gs5[(b * 8 + g) * 2 + 1], c);
    }
}

// ---------------- final head: GN + relu + max-over-N via endpoints ----------------
__global__ void final_out_kernel(const float* __restrict__ gnw,
                                 const float* __restrict__ gnb,
                                 float* __restrict__ out) {
    int i = blockIdx.x * 256 + threadIdx.x;
    if (i >= B * 1024) return;
    int b = i >> 10, c = i & 1023;
    int g = c >> 7;
    double cnt = 128.0 * 1024.0;
    double S1 = g_gs5[(b * 8 + g) * 2 + 0], S2 = g_gs5[(b * 8 + g) * 2 + 1];
    double mud = S1 / cnt;
    float var = (float)(S2 / cnt - mud * mud);
    float mu = (float)mud;
    float rs = rsqrtf(var + 1e-5f);
    float a = gnw[c] * rs;
    float bb = gnb[c] - mu * a;
    float ymx = fdec(g_ymax[i]), ymn = fdec(g_ymin[i]);
    float c1 = fmaxf(fmaf(a, ymx, bb), 0.f);
    float c2 = fmaxf(fmaf(a, ymn, bb), 0.f);
    out[i] = fmaxf(c1, c2);
}

// ---------------- launch ----------------
extern "C" void kernel_launch(void* const* d_in, const int* in_sizes, int n_in,
                              void* d_out, int out_size) {
    const float* x    = (const float*)d_in[0];
    const float* c1w  = (const float*)d_in[1];
    const float* g1w  = (const float*)d_in[2];
    const float* g1b  = (const float*)d_in[3];
    const float* c2w  = (const float*)d_in[4];
    const float* g2w  = (const float*)d_in[5];
    const float* g2b  = (const float*)d_in[6];
    const float* c3w  = (const float*)d_in[7];
    const float* g3w  = (const float*)d_in[8];
    const float* g3b  = (const float*)d_in[9];
    const float* mlpw = (const float*)d_in[10];
    const float* mlpb = (const float*)d_in[11];
    const float* g5w  = (const float*)d_in[12];
    const float* g5b  = (const float*)d_in[13];

    float* out  = (float*)d_out;
    float* feat = out + B * 1024;  // x_features region (B,256,N)

    struct L { const float* xin; int bstride, Cin, Cout, choff, gsoff;
               const float* W; const float* gw; const float* gb; };
    L layers[3] = {
        { x,                3 * NPTS,   3,   64, 0,   0,  c1w, g1w, g1b },
        { feat,             256 * NPTS, 64,  64, 64,  16, c2w, g2w, g2b },
        { feat + 64 * NPTS, 256 * NPTS, 64,  128, 128, 32, c3w, g3w, g3b },
    };

    zero_all_kernel<<<16, 256>>>();

    for (int li = 0; li < 3; li++) {
        L& l = layers[li];
        gram_kernel<<<dim3(8, 8, B), 256>>>(l.xin, l.bstride, l.Cin);
        knn_kernel<<<B * NPTS, 256>>>();
        int tot = B * NPTS * l.Cout;
        uv_kernel<<<tot / 256, 256>>>(l.xin, l.bstride, l.W, l.Cin, l.Cout);
        int ppb = 256 / (l.Cout >> 2);
        edge_agg_kernel<<<B * NPTS / ppb, 256>>>(l.Cout, l.gsoff);
        edge_out_kernel<<<B * l.Cout, 256>>>(l.Cout, l.gsoff, l.gw, l.gb, feat, l.choff);
    }

    final_mm_kernel<<<dim3(8, 8, B), 256>>>(feat, mlpw, mlpb);
    final_out_kernel<<<16, 256>>>(g5w, g5b, out);
}